// round 5
// baseline (speedup 1.0000x reference)
#include <cuda_runtime.h>
#include <cuda_fp16.h>
#include <cuda_bf16.h>
#include <cstdint>

#define BB 4
#define NN 8192
#define KK 16
#define DD 128
#define GG 32
#define MM (BB*NN)          // 32768 rows
#define BN_EPS 1e-5f

#define NPART 4096          // gather blocks = stats partials

// ---------------- scratch (device globals; no allocation) ----------------
__device__ __half g_h[(size_t)MM * DD];       // projected features, fp16, 8 MB
__device__ __half g_agg[(size_t)MM * DD];     // pre-norm aggregate, fp16, 8 MB
__device__ float g_psum [NPART][DD];          // per-gather-block partial sums
__device__ float g_psum2[NPART][DD];          // per-gather-block partial sumsq
__device__ float g_scale[DD];                 // fused BN scale
__device__ float g_shift[DD];                 // fused BN shift

// ---------------- mma / ldmatrix helpers ----------------------------------
#define LDSM4(r0, r1, r2, r3, addr)                                            \
    asm volatile("ldmatrix.sync.aligned.m8n8.x4.shared.b16 {%0,%1,%2,%3}, [%4];" \
                 : "=r"(r0), "=r"(r1), "=r"(r2), "=r"(r3) : "r"(addr))

__device__ __forceinline__ void mma_bf16(float c[4],
                                         uint32_t a0, uint32_t a1, uint32_t a2, uint32_t a3,
                                         uint32_t b0, uint32_t b1) {
    asm volatile(
        "mma.sync.aligned.m16n8k16.row.col.f32.bf16.bf16.f32 "
        "{%0,%1,%2,%3}, {%4,%5,%6,%7}, {%8,%9}, {%0,%1,%2,%3};"
        : "+f"(c[0]), "+f"(c[1]), "+f"(c[2]), "+f"(c[3])
        : "r"(a0), "r"(a1), "r"(a2), "r"(a3), "r"(b0), "r"(b1));
}

// ---------------- kernel 1: H = X * W^T, split-bf16 3-MMA -----------------
// Block 256 thr (8 warps: wm 0..3, wn 0..1). Tile M128 x N128, warp 32x64.
// K staged by 32 (2 k16 MMA steps per stage), register prefetch of next
// stage's global loads overlapped with the MMA section.
#define BK 32
#define RS 40   // smem row stride in bf16 elems (80 B -> LDSM conflict-free)
__global__ void __launch_bounds__(256) gemm_kernel(const float* __restrict__ X,
                                                   const float* __restrict__ W,
                                                   __half* __restrict__ H) {
    __shared__ __nv_bfloat16 Xhi[128 * RS];
    __shared__ __nv_bfloat16 Xlo[128 * RS];
    __shared__ __nv_bfloat16 Whi[128 * RS];
    __shared__ __nv_bfloat16 Wlo[128 * RS];

    const int tid  = threadIdx.x;
    const int warp = tid >> 5;
    const int lane = tid & 31;
    const int wm   = warp >> 1;          // 0..3 -> M offset wm*32
    const int wn   = warp & 1;           // 0..1 -> N offset wn*64
    const int m0   = blockIdx.x * 128;
    const int gr   = lane >> 2;          // groupID 0..7
    const int gc   = lane & 3;           // tig 0..3
    const int l16  = lane & 15;
    const int kh   = (lane >> 4) << 3;   // 0 or 8 (k half for ldmatrix)

    float c[2][8][4];
#pragma unroll
    for (int i = 0; i < 2; i++)
#pragma unroll
        for (int j = 0; j < 8; j++)
#pragma unroll
            for (int t = 0; t < 4; t++) c[i][j][t] = 0.f;

    const uint32_t xhi_b = (uint32_t)__cvta_generic_to_shared(Xhi);
    const uint32_t xlo_b = (uint32_t)__cvta_generic_to_shared(Xlo);
    const uint32_t whi_b = (uint32_t)__cvta_generic_to_shared(Whi);
    const uint32_t wlo_b = (uint32_t)__cvta_generic_to_shared(Wlo);

    float4 px[4], pw[4];
    // prologue: prefetch stage 0
#pragma unroll
    for (int i = 0; i < 4; i++) {
        const int q   = tid + i * 256;
        const int row = q >> 3;
        const int cq  = q & 7;
        px[i] = *(const float4*)(X + (size_t)(m0 + row) * DD + cq * 4);
        pw[i] = *(const float4*)(W + (size_t)row * DD + cq * 4);
    }

    for (int kcs = 0; kcs < DD / BK; kcs++) {
        // convert + store current stage
#pragma unroll
        for (int i = 0; i < 4; i++) {
            const int q   = tid + i * 256;
            const int row = q >> 3;
            const int cq  = q & 7;
            {
                const float4 v = px[i];
                __nv_bfloat16 hx = __float2bfloat16(v.x);
                __nv_bfloat16 hy = __float2bfloat16(v.y);
                __nv_bfloat16 hz = __float2bfloat16(v.z);
                __nv_bfloat16 hw = __float2bfloat16(v.w);
                __nv_bfloat162 hp0 = __halves2bfloat162(hx, hy);
                __nv_bfloat162 hp1 = __halves2bfloat162(hz, hw);
                __nv_bfloat162 lp0 = __halves2bfloat162(
                    __float2bfloat16(v.x - __bfloat162float(hx)),
                    __float2bfloat16(v.y - __bfloat162float(hy)));
                __nv_bfloat162 lp1 = __halves2bfloat162(
                    __float2bfloat16(v.z - __bfloat162float(hz)),
                    __float2bfloat16(v.w - __bfloat162float(hw)));
                *(uint2*)&Xhi[row * RS + cq * 4] =
                    make_uint2(*(uint32_t*)&hp0, *(uint32_t*)&hp1);
                *(uint2*)&Xlo[row * RS + cq * 4] =
                    make_uint2(*(uint32_t*)&lp0, *(uint32_t*)&lp1);
            }
            {
                const float4 v = pw[i];
                __nv_bfloat16 hx = __float2bfloat16(v.x);
                __nv_bfloat16 hy = __float2bfloat16(v.y);
                __nv_bfloat16 hz = __float2bfloat16(v.z);
                __nv_bfloat16 hw = __float2bfloat16(v.w);
                __nv_bfloat162 hp0 = __halves2bfloat162(hx, hy);
                __nv_bfloat162 hp1 = __halves2bfloat162(hz, hw);
                __nv_bfloat162 lp0 = __halves2bfloat162(
                    __float2bfloat16(v.x - __bfloat162float(hx)),
                    __float2bfloat16(v.y - __bfloat162float(hy)));
                __nv_bfloat162 lp1 = __halves2bfloat162(
                    __float2bfloat16(v.z - __bfloat162float(hz)),
                    __float2bfloat16(v.w - __bfloat162float(hw)));
                *(uint2*)&Whi[row * RS + cq * 4] =
                    make_uint2(*(uint32_t*)&hp0, *(uint32_t*)&hp1);
                *(uint2*)&Wlo[row * RS + cq * 4] =
                    make_uint2(*(uint32_t*)&lp0, *(uint32_t*)&lp1);
            }
        }
        __syncthreads();

        // prefetch next stage (LDG latency overlaps MMA below)
        if (kcs + 1 < DD / BK) {
            const int kc = (kcs + 1) * BK;
#pragma unroll
            for (int i = 0; i < 4; i++) {
                const int q   = tid + i * 256;
                const int row = q >> 3;
                const int cq  = q & 7;
                px[i] = *(const float4*)(X + (size_t)(m0 + row) * DD + kc + cq * 4);
                pw[i] = *(const float4*)(W + (size_t)row * DD + kc + cq * 4);
            }
        }

#pragma unroll
        for (int s = 0; s < BK / 16; s++) {
            const uint32_t koff = (kh + s * 16) * 2;

            uint32_t ahi[2][4], alo[2][4];
#pragma unroll
            for (int am = 0; am < 2; am++) {
                const uint32_t ro = (uint32_t)(wm * 32 + am * 16 + l16) * (RS * 2) + koff;
                LDSM4(ahi[am][0], ahi[am][1], ahi[am][2], ahi[am][3], xhi_b + ro);
                LDSM4(alo[am][0], alo[am][1], alo[am][2], alo[am][3], xlo_b + ro);
            }
            uint32_t bhi[4][4], blo[4][4];
#pragma unroll
            for (int p = 0; p < 4; p++) {
                const uint32_t ro = (uint32_t)(wn * 64 + p * 16 + l16) * (RS * 2) + koff;
                LDSM4(bhi[p][0], bhi[p][1], bhi[p][2], bhi[p][3], whi_b + ro);
                LDSM4(blo[p][0], blo[p][1], blo[p][2], blo[p][3], wlo_b + ro);
            }

#pragma unroll
            for (int p = 0; p < 4; p++)
#pragma unroll
                for (int e = 0; e < 2; e++) {
                    const int an = 2 * p + e;
                    const uint32_t bh0 = bhi[p][e], bh1 = bhi[p][2 + e];
                    const uint32_t bl0 = blo[p][e], bl1 = blo[p][2 + e];
#pragma unroll
                    for (int am = 0; am < 2; am++) {
                        mma_bf16(c[am][an], ahi[am][0], ahi[am][1], ahi[am][2], ahi[am][3], bh0, bh1);
                        mma_bf16(c[am][an], ahi[am][0], ahi[am][1], ahi[am][2], ahi[am][3], bl0, bl1);
                        mma_bf16(c[am][an], alo[am][0], alo[am][1], alo[am][2], alo[am][3], bh0, bh1);
                    }
                }
        }
        __syncthreads();
    }

    // epilogue -> fp16 H
#pragma unroll
    for (int am = 0; am < 2; am++) {
        const int row = m0 + wm * 32 + am * 16 + gr;
#pragma unroll
        for (int an = 0; an < 8; an++) {
            const int col = wn * 64 + an * 8 + 2 * gc;
            *(__half2*)(H + (size_t)row * DD + col) =
                __floats2half2_rn(c[am][an][0], c[am][an][1]);
            *(__half2*)(H + (size_t)(row + 8) * DD + col) =
                __floats2half2_rn(c[am][an][2], c[am][an][3]);
        }
    }
}

// ---------------- kernel 2: gather + encoding + max + stats partials ------
// One warp per point, 8 points/block. Lane g owns channels [4g,4g+4).
// Writes fp16 agg; stats computed on the ROUNDED values for consistency.
__global__ void __launch_bounds__(256) gather_kernel(const __half* __restrict__ H,
                                                     const float* __restrict__ xyz,
                                                     const int* __restrict__ knn,
                                                     const float* __restrict__ coor,
                                                     const float* __restrict__ scale,
                                                     __half* __restrict__ agg) {
    __shared__ float sh_s[8][132];
    __shared__ float sh_q[8][132];

    const int warp = (blockIdx.x * blockDim.x + threadIdx.x) >> 5;
    const int wloc = threadIdx.x >> 5;
    const int lane = threadIdx.x & 31;

    const int b = warp >> 13;          // warp / 8192
    const int base = b << 13;          // b*N

    const float wx = coor[3 * lane + 0];
    const float wy = coor[3 * lane + 1];
    const float wz = coor[3 * lane + 2];
    const float sv = scale[lane];
    const float ws = sv * sv;

    const float* cptr = xyz + (size_t)warp * 3;
    const float cx = cptr[0], cy = cptr[1], cz = cptr[2];

    const int nb = knn[(size_t)warp * KK + (lane & 15)];

    float4 acc = make_float4(-3.402823466e38f, -3.402823466e38f,
                             -3.402823466e38f, -3.402823466e38f);

#pragma unroll
    for (int k = 0; k < KK; k++) {
        const int idx = __shfl_sync(0xffffffffu, nb, k);
        const int row = base + idx;
        const float* nx = xyz + (size_t)row * 3;
        const float rx = nx[0] - cx;
        const float ry = nx[1] - cy;
        const float rz = nx[2] - cz;
        const float r2 = fmaf(rx, rx, fmaf(ry, ry, rz * rz));
        const float e  = fmaf(rx, wx, fmaf(ry, wy, fmaf(rz, wz, r2 * ws)));
        const uint2 hv = *(const uint2*)(H + (size_t)row * DD + lane * 4);
        const float2 f0 = __half22float2(*(const __half2*)&hv.x);
        const float2 f1 = __half22float2(*(const __half2*)&hv.y);
        acc.x = fmaxf(acc.x, f0.x + e);
        acc.y = fmaxf(acc.y, f0.y + e);
        acc.z = fmaxf(acc.z, f1.x + e);
        acc.w = fmaxf(acc.w, f1.y + e);
    }

    const __half2 p0 = __floats2half2_rn(acc.x, acc.y);
    const __half2 p1 = __floats2half2_rn(acc.z, acc.w);
    uint2 pk;
    pk.x = *(const uint32_t*)&p0;
    pk.y = *(const uint32_t*)&p1;
    *(uint2*)(agg + (size_t)warp * DD + lane * 4) = pk;

    // rounded-back values for stats (consistent with what norm will read)
    const float2 r0 = __half22float2(p0);
    const float2 r1 = __half22float2(p1);

    sh_s[wloc][lane * 4 + 0] = r0.x;
    sh_s[wloc][lane * 4 + 1] = r0.y;
    sh_s[wloc][lane * 4 + 2] = r1.x;
    sh_s[wloc][lane * 4 + 3] = r1.y;
    sh_q[wloc][lane * 4 + 0] = r0.x * r0.x;
    sh_q[wloc][lane * 4 + 1] = r0.y * r0.y;
    sh_q[wloc][lane * 4 + 2] = r1.x * r1.x;
    sh_q[wloc][lane * 4 + 3] = r1.y * r1.y;
    __syncthreads();

    if (threadIdx.x < 128) {
        const int ch = threadIdx.x;
        float s = 0.f;
#pragma unroll
        for (int w = 0; w < 8; w++) s += sh_s[w][ch];
        g_psum[blockIdx.x][ch] = s;
    } else {
        const int ch = threadIdx.x - 128;
        float q = 0.f;
#pragma unroll
        for (int w = 0; w < 8; w++) q += sh_q[w][ch];
        g_psum2[blockIdx.x][ch] = q;
    }
}

// ---------------- kernel 3: stats finalize (one block per channel) --------
__global__ void __launch_bounds__(256) stats2_kernel(const float* __restrict__ bn_w,
                                                     const float* __restrict__ bn_b) {
    __shared__ float rs[256], rq[256];
    const int ch  = blockIdx.x;
    const int tid = threadIdx.x;

    float s = 0.f, q = 0.f;
    for (int p = tid; p < NPART; p += 256) {
        s += g_psum[p][ch];
        q += g_psum2[p][ch];
    }
    rs[tid] = s;
    rq[tid] = q;
    __syncthreads();
#pragma unroll
    for (int st = 128; st > 0; st >>= 1) {
        if (tid < st) {
            rs[tid] += rs[tid + st];
            rq[tid] += rq[tid + st];
        }
        __syncthreads();
    }
    if (tid == 0) {
        const float inv_m = 1.f / (float)MM;
        const float mean = rs[0] * inv_m;
        const float var  = fmaf(-mean, mean, rq[0] * inv_m);
        const float a = bn_w[ch] * rsqrtf(var + BN_EPS);
        g_scale[ch] = a;
        g_shift[ch] = fmaf(-mean, a, bn_b[ch]);
    }
}

// ---------------- kernel 4: normalize fp16 agg -> fp32 out ----------------
// Grid stride is a multiple of 32 float4s, so each thread's channel group is
// invariant: hoist scale/shift into registers.
__global__ void __launch_bounds__(256) norm_kernel(const __half* __restrict__ agg,
                                                   float* __restrict__ out) {
    const int t0 = blockIdx.x * blockDim.x + threadIdx.x;
    const int c0 = (t0 & 31) * 4;
    const float s0 = g_scale[c0 + 0], s1 = g_scale[c0 + 1];
    const float s2 = g_scale[c0 + 2], s3 = g_scale[c0 + 3];
    const float b0 = g_shift[c0 + 0], b1 = g_shift[c0 + 1];
    const float b2 = g_shift[c0 + 2], b3 = g_shift[c0 + 3];

    const int total  = MM * (DD / 4);           // 1M float4 outputs
    const int stride = gridDim.x * blockDim.x;  // multiple of 32

    for (int t = t0; t < total; t += stride) {
        const uint2 hv = __ldcs((const uint2*)(agg) + t);
        const float2 f0 = __half22float2(*(const __half2*)&hv.x);
        const float2 f1 = __half22float2(*(const __half2*)&hv.y);
        float4 v;
        v.x = fmaf(f0.x, s0, b0);
        v.y = fmaf(f0.y, s1, b1);
        v.z = fmaf(f1.x, s2, b2);
        v.w = fmaf(f1.y, s3, b3);
        __stcs((float4*)out + t, v);
    }
}

// ---------------- launch ---------------------------------------------------
extern "C" void kernel_launch(void* const* d_in, const int* in_sizes, int n_in,
                              void* d_out, int out_size) {
    const float* x      = (const float*)d_in[0];
    const float* xyz    = (const float*)d_in[1];
    const int*   knn    = (const int*)  d_in[2];
    const float* proj_w = (const float*)d_in[3];
    const float* coor   = (const float*)d_in[4];
    const float* scale  = (const float*)d_in[5];
    const float* bn_w   = (const float*)d_in[6];
    const float* bn_b   = (const float*)d_in[7];
    float* out = (float*)d_out;

    __half* h;
    __half* agg;
    cudaGetSymbolAddress((void**)&h, g_h);
    cudaGetSymbolAddress((void**)&agg, g_agg);

    gemm_kernel<<<MM / 128, 256>>>(x, proj_w, h);
    gather_kernel<<<MM / 8, 256>>>(h, xyz, knn, coor, scale, agg);
    stats2_kernel<<<DD, 256>>>(bn_w, bn_b);
    norm_kernel<<<1024, 256>>>(agg, out);
}